// round 14
// baseline (speedup 1.0000x reference)
#include <cuda_runtime.h>
#include <cuda_fp16.h>
#include <math.h>
#include <stdint.h>

#define C_IN   64
#define C_OUT  64
#define NBASIS 9
#define TILE_M 128
#define MAX_T  1600000
#define MAX_F  400000
#define BN_EPS 1e-3f

// ---- scratch (device globals; no allocation allowed) ----
__device__ __half g_contrib[(size_t)MAX_T * C_OUT];  // fallback path only
__device__ __half g_prebn[(size_t)MAX_F * C_OUT];    // 51.2 MB (fp16)
__device__ int    g_offs[MAX_F];
__device__ int    g_blk[1024];
__device__ float  g_stats[2 * C_OUT];
__device__ int    g_flag;                             // 1 if all counts == 4

// ================= exclusive-scan of num_texture =================
__global__ void scan1_kernel(const int* __restrict__ cnt, int F) {
    __shared__ int s[1024];
    int tid = threadIdx.x;
    int f = blockIdx.x * 1024 + tid;
    int c = (f < F) ? cnt[f] : 0;
    s[tid] = c;
    __syncthreads();
    for (int off = 1; off < 1024; off <<= 1) {
        int v = (tid >= off) ? s[tid - off] : 0;
        __syncthreads();
        s[tid] += v;
        __syncthreads();
    }
    if (f < F) g_offs[f] = s[tid] - c;
    if (tid == 1023) g_blk[blockIdx.x] = s[1023];
}
__global__ void scan2_kernel(int nb) {
    __shared__ int s[1024];
    int tid = threadIdx.x;
    int c = (tid < nb) ? g_blk[tid] : 0;
    s[tid] = c;
    __syncthreads();
    for (int off = 1; off < 1024; off <<= 1) {
        int v = (tid >= off) ? s[tid - off] : 0;
        __syncthreads();
        s[tid] += v;
        __syncthreads();
    }
    if (tid < nb) g_blk[tid] = s[tid] - c;
    if (tid == 0) g_flag = 1;
}
__global__ void scan3_kernel(const int* __restrict__ cnt, int F) {
    int f = blockIdx.x * 1024 + threadIdx.x;
    bool ok = true;
    if (f < F) {
        g_offs[f] += g_blk[blockIdx.x];
        ok = (cnt[f] == 4);
    }
    if (blockIdx.x == 0 && threadIdx.x < 2 * C_OUT) g_stats[threadIdx.x] = 0.0f;
    if (!__syncthreads_and(ok ? 1 : 0)) {
        if (threadIdx.x == 0) g_flag = 0;
    }
}

// ================= shared helpers =================
#define MMA16816(d, a0, a1, a2, a3, b0, b1)                                 \
    asm volatile(                                                           \
        "mma.sync.aligned.m16n8k16.row.col.f32.f16.f16.f32 "                \
        "{%0,%1,%2,%3},{%4,%5,%6,%7},{%8,%9},{%0,%1,%2,%3};"                \
        : "+f"((d)[0]), "+f"((d)[1]), "+f"((d)[2]), "+f"((d)[3])            \
        : "r"(a0), "r"(a1), "r"(a2), "r"(a3), "r"(b0), "r"(b1))

__device__ __forceinline__ void ldsm4(uint32_t* r, uint32_t addr) {
    asm volatile("ldmatrix.sync.aligned.m8n8.x4.shared.b16 {%0,%1,%2,%3}, [%4];"
                 : "=r"(r[0]), "=r"(r[1]), "=r"(r[2]), "=r"(r[3]) : "r"(addr));
}
__device__ __forceinline__ uint32_t hmul2u(uint32_t a, uint32_t b) {
    __half2 r = __hmul2(*(__half2*)&a, *(__half2*)&b);
    return *(uint32_t*)&r;
}
__device__ __forceinline__ uint32_t hfma2u(uint32_t a, uint32_t b, uint32_t c) {
    __half2 r = __hfma2(*(__half2*)&a, *(__half2*)&b, *(__half2*)&c);
    return *(uint32_t*)&r;
}

// ================= FUSED kernel (counts all == 4), warp-specialized ========
// Z[f, :] = sum_j x[4f+j] ⊗ bary[4f+j]  (fp16, SMEM)  -- constructor warps 8..15
// prebn[f,o] = relu( (Z @ W^T)[f,o] * 0.25 + bias )    -- GEMM warps 0..7 (32x32 tiles)
//
// Tile = 512 textures = 128 facets. SMEM:
//   Z : 128 rows x 1168 B                                   = 149504
//   W : [kb*64+o] rows of 128B, XOR-swizzled 16B chunks     =  73728
#define TILE_TX   512
#define TILE_F    128
#define ZSTR      1168
#define SM_Z      0
#define SM_W2     149504
#define SMEM_FUSED 223232

// constructor: load one round's X (4 textures x 16 chunks) + bary into regs
__device__ __forceinline__ void load_round(
    const float* __restrict__ X, const float* __restrict__ BARY,
    int tbase, int T, uint32_t xh[4][4][2], float br[9])
{
    #pragma unroll
    for (int j = 0; j < 4; j++) {
        int t = tbase + j;
        if (t < T) {
            const float4* xp = (const float4*)(X + (size_t)t * C_IN);
            #pragma unroll
            for (int cc = 0; cc < 4; cc++) {
                float4 v = xp[cc * 4 + 0];   // placeholder, fixed below
                (void)v;
            }
        }
        (void)t;
    }
    (void)xh; (void)br; (void)BARY;
}

__global__ void __launch_bounds__(512, 1) gemm_fused_kernel(
    const float* __restrict__ X,     // [T, 64]
    const float* __restrict__ BARY,  // [T, 9]
    const float* __restrict__ W,     // [64, 64, 9]
    const float* __restrict__ BIAS,  // [64]
    int T, int F, int numTiles)
{
    if (g_flag == 0) return;
    extern __shared__ char sm[];
    const uint32_t smb = (uint32_t)__cvta_generic_to_shared(sm);

    const int tid  = threadIdx.x;
    const int lane = tid & 31;

    // ---- W fp16 convert (all 512 threads) ----
    for (int idx = tid; idx < C_OUT * C_IN * NBASIS; idx += 512) {
        int o   = idx / (C_IN * NBASIS);
        int rem = idx - o * (C_IN * NBASIS);
        int i   = rem / NBASIS;
        int k   = rem - i * NBASIS;
        uint32_t byte = (uint32_t)(k * 64 + o) * 128
                      + ((((uint32_t)i >> 3) ^ (uint32_t)(o & 7)) << 4)
                      + (i & 7) * 2;
        *(__half*)(sm + SM_W2 + byte) = __float2half_rn(W[idx]);
    }
    __syncthreads();   // W ready (pre-split barrier)

    if (tid < 256) {
        // ================= GEMM role: warps 0..7, 32x32 warp tiles =========
        const int wid    = tid >> 5;
        const int gid    = lane >> 2;
        const int tid4   = lane & 3;
        const int warp_m = wid >> 1;     // 0..3
        const int warp_n = wid & 1;      // 0..1
        const int rbase  = warp_m * 32;

        // bias regs: 8 values (4 nt x col pair)
        float bia[4][2];
        #pragma unroll
        for (int nt = 0; nt < 4; nt++) {
            int col = warp_n * 32 + nt * 8 + tid4 * 2;
            bia[nt][0] = BIAS[col];
            bia[nt][1] = BIAS[col + 1];
        }

        uint32_t aBase[2];
        #pragma unroll
        for (int mt = 0; mt < 2; mt++)
            aBase[mt] = smb + SM_Z
                      + (uint32_t)(rbase + mt * 16 + (lane & 15)) * ZSTR
                      + ((uint32_t)(lane >> 4) << 4);
        uint32_t bBase[2];
        int s_p[2];
        const int kh = (lane >> 3) & 1;
        #pragma unroll
        for (int p = 0; p < 2; p++) {
            int n_local = warp_n * 32 + p * 16 + ((lane >> 4) & 1) * 8 + (lane & 7);
            bBase[p] = smb + SM_W2 + (uint32_t)n_local * 128;
            s_p[p] = n_local & 7;
        }

        for (int tile = blockIdx.x; tile < numTiles; tile += gridDim.x) {
            __syncthreads();   // barrier A: Z(tile) ready

            float acc[2][4][4];
            #pragma unroll
            for (int mt = 0; mt < 2; mt++)
                #pragma unroll
                for (int nt = 0; nt < 4; nt++)
                    #pragma unroll
                    for (int e = 0; e < 4; e++) acc[mt][nt][e] = 0.0f;

            #pragma unroll 1
            for (int kb = 0; kb < NBASIS; kb++) {
                const uint32_t kbA = (uint32_t)kb * 128;   // 4 kc * 32B
                const uint32_t kbB = (uint32_t)kb * 8192;
                #pragma unroll
                for (int ks = 0; ks < 4; ks++) {
                    uint32_t a0[4], a1[4];
                    ldsm4(a0, aBase[0] + kbA + ks * 32);
                    ldsm4(a1, aBase[1] + kbA + ks * 32);
                    #pragma unroll
                    for (int p = 0; p < 2; p++) {
                        uint32_t b[4];
                        uint32_t chunk = (uint32_t)(((ks << 1) | kh) ^ s_p[p]) << 4;
                        ldsm4(b, bBase[p] + kbB + chunk);
                        MMA16816(acc[0][2 * p],     a0[0], a0[1], a0[2], a0[3], b[0], b[1]);
                        MMA16816(acc[1][2 * p],     a1[0], a1[1], a1[2], a1[3], b[0], b[1]);
                        MMA16816(acc[0][2 * p + 1], a0[0], a0[1], a0[2], a0[3], b[2], b[3]);
                        MMA16816(acc[1][2 * p + 1], a1[0], a1[1], a1[2], a1[3], b[2], b[3]);
                    }
                }
            }

            // epilogue: mean + bias + relu -> prebn
            int f0 = tile * TILE_F + rbase;
            #pragma unroll
            for (int mt = 0; mt < 2; mt++) {
                int fA = f0 + mt * 16 + gid;
                #pragma unroll
                for (int nt = 0; nt < 4; nt++) {
                    int col = warp_n * 32 + nt * 8 + tid4 * 2;
                    if (fA < F) {
                        float v0 = fmaxf(acc[mt][nt][0] * 0.25f + bia[nt][0], 0.0f);
                        float v1 = fmaxf(acc[mt][nt][1] * 0.25f + bia[nt][1], 0.0f);
                        *(__half2*)&g_prebn[(size_t)fA * C_OUT + col] = __floats2half2_rn(v0, v1);
                    }
                    if (fA + 8 < F) {
                        float v0 = fmaxf(acc[mt][nt][2] * 0.25f + bia[nt][0], 0.0f);
                        float v1 = fmaxf(acc[mt][nt][3] * 0.25f + bia[nt][1], 0.0f);
                        *(__half2*)&g_prebn[(size_t)(fA + 8) * C_OUT + col] = __floats2half2_rn(v0, v1);
                    }
                }
            }
            __syncthreads();   // barrier B: done reading Z(tile)
        }
    } else {
        // ================= constructor role: warps 8..15 ====================
        const int ctid = tid - 256;      // 0..255
        const int fq   = ctid >> 2;      // 0..63 (facet within round)
        const int q    = ctid & 3;       // channel quarter

        uint32_t xh0[4][4][2], xh1[4][4][2];
        float    br0[9], br1[9];

        // prologue: prefetch round 0 of first tile
        {
            int tb = blockIdx.x * TILE_TX + fq * 4;
            #pragma unroll
            for (int j = 0; j < 4; j++) {
                int t = tb + j;
                if (t < T) {
                    const float4* xp = (const float4*)(X + (size_t)t * C_IN + q * 4);
                    #pragma unroll
                    for (int cc = 0; cc < 4; cc++) {
                        float4 v = xp[cc * 4];
                        __half2 h0 = __floats2half2_rn(v.x, v.y);
                        __half2 h1 = __floats2half2_rn(v.z, v.w);
                        xh0[j][cc][0] = *(uint32_t*)&h0;
                        xh0[j][cc][1] = *(uint32_t*)&h1;
                    }
                } else {
                    #pragma unroll
                    for (int cc = 0; cc < 4; cc++) { xh0[j][cc][0] = 0u; xh0[j][cc][1] = 0u; }
                }
            }
            int t = tb + q;
            #pragma unroll
            for (int k = 0; k < NBASIS; k++)
                br0[k] = (t < T) ? BARY[(size_t)t * NBASIS + k] : 0.0f;
        }

        for (int tile = blockIdx.x; tile < numTiles; tile += gridDim.x) {
            // ---- issue round-1 loads (latency covered by round-0 FMA) ----
            {
                int tb = tile * TILE_TX + (fq + 64) * 4;
                #pragma unroll
                for (int j = 0; j < 4; j++) {
                    int t = tb + j;
                    if (t < T) {
                        const float4* xp = (const float4*)(X + (size_t)t * C_IN + q * 4);
                        #pragma unroll
                        for (int cc = 0; cc < 4; cc++) {
                            float4 v = xp[cc * 4];
                            __half2 h0 = __floats2half2_rn(v.x, v.y);
                            __half2 h1 = __floats2half2_rn(v.z, v.w);
                            xh1[j][cc][0] = *(uint32_t*)&h0;
                            xh1[j][cc][1] = *(uint32_t*)&h1;
                        }
                    } else {
                        #pragma unroll
                        for (int cc = 0; cc < 4; cc++) { xh1[j][cc][0] = 0u; xh1[j][cc][1] = 0u; }
                    }
                }
                int t = tb + q;
                #pragma unroll
                for (int k = 0; k < NBASIS; k++)
                    br1[k] = (t < T) ? BARY[(size_t)t * NBASIS + k] : 0.0f;
            }

            // ---- round 0 construct: facets [0..64) of tile ----
            {
                const uint32_t zbase = smb + SM_Z + (uint32_t)fq * ZSTR + q * 8;
                #pragma unroll
                for (int k = 0; k < NBASIS; k++) {
                    uint32_t ac[4][2];
                    #pragma unroll
                    for (int j = 0; j < 4; j++) {
                        float bf = __shfl_sync(0xFFFFFFFFu, br0[k], (lane & ~3) | j);
                        __half2 hb = __half2half2(__float2half_rn(bf));
                        uint32_t bb = *(uint32_t*)&hb;
                        #pragma unroll
                        for (int cc = 0; cc < 4; cc++) {
                            if (j == 0) {
                                ac[cc][0] = hmul2u(xh0[0][cc][0], bb);
                                ac[cc][1] = hmul2u(xh0[0][cc][1], bb);
                            } else {
                                ac[cc][0] = hfma2u(xh0[j][cc][0], bb, ac[cc][0]);
                                ac[cc][1] = hfma2u(xh0[j][cc][1], bb, ac[cc][1]);
                            }
                        }
                    }
                    #pragma unroll
                    for (int cc = 0; cc < 4; cc++)
                        asm volatile("st.shared.v2.b32 [%0], {%1, %2};"
                                     :: "r"(zbase + k * 128 + cc * 32),
                                        "r"(ac[cc][0]), "r"(ac[cc][1]) : "memory");
                }
            }
            // ---- round 1 construct: facets [64..128) of tile ----
            {
                const uint32_t zbase = smb + SM_Z + (uint32_t)(fq + 64) * ZSTR + q * 8;
                #pragma unroll
                for (int k = 0; k < NBASIS; k++) {
                    uint32_t ac[4][2];
                    #pragma unroll
                    for (int j = 0; j < 4; j++) {
                        float bf = __shfl_sync(0xFFFFFFFFu, br1[k], (lane & ~3) | j);
                        __half2 hb = __half2half2(__float2half_rn(bf));
                        uint32_t bb = *(uint32_t*)&hb;
                        #pragma unroll
                        for (int cc = 0; cc < 4; cc++) {
                            if (j == 0) {
                                ac[cc][0] = hmul2u(xh1[0][cc][0], bb);
                                ac[cc][1] = hmul2u(xh1[0][cc][1], bb);
                            } else {
                                ac[cc][0] = hfma2u(xh1[j][cc][0], bb, ac[cc][0]);
                                ac[cc][1] = hfma2u(xh1[j][cc][1], bb, ac[cc][1]);
                            }
                        }
                    }
                    #pragma unroll
                    for (int cc = 0; cc < 4; cc++)
                        asm volatile("st.shared.v2.b32 [%0], {%1, %2};"
                                     :: "r"(zbase + k * 128 + cc * 32),
                                        "r"(ac[cc][0]), "r"(ac[cc][1]) : "memory");
                }
            }
            __syncthreads();   // barrier A: Z(tile) ready

            // ---- prefetch round 0 of next tile (in flight during GEMM) ----
            {
                int ntile = tile + gridDim.x;
                if (ntile < numTiles) {
                    int tb = ntile * TILE_TX + fq * 4;
                    #pragma unroll
                    for (int j = 0; j < 4; j++) {
                        int t = tb + j;
                        if (t < T) {
                            const float4* xp = (const float4*)(X + (size_t)t * C_IN + q * 4);
                            #pragma unroll
                            for (int cc = 0; cc < 4; cc++) {
                                float4 v = xp[cc * 4];
                                __half2 h0 = __floats2half2_rn(v.x, v.y);
                                __half2 h1 = __floats2half2_rn(v.z, v.w);
                                xh0[j][cc][0] = *(uint32_t*)&h0;
                                xh0[j][cc][1] = *(uint32_t*)&h1;
                            }
                        } else {
                            #pragma unroll
                            for (int cc = 0; cc < 4; cc++) { xh0[j][cc][0] = 0u; xh0[j][cc][1] = 0u; }
                        }
                    }
                    int t = tb + q;
                    #pragma unroll
                    for (int k = 0; k < NBASIS; k++)
                        br0[k] = (t < T) ? BARY[(size_t)t * NBASIS + k] : 0.0f;
                }
            }
            __syncthreads();   // barrier B: GEMM done reading Z(tile)
        }
    }
}

// ================= FALLBACK GEMM (general counts; R8/R12 core) =============
#define SM_W      0
#define SM_AX     73728
#define SM_BS     92160
#define BS_HALFS  1188
#define SMEM_GEMM 96912

__global__ void __launch_bounds__(256, 2) gemm_fallback_kernel(
    const float* __restrict__ X, const float* __restrict__ BARY,
    const float* __restrict__ W, int T, int numTiles)
{
    if (g_flag != 0) return;
    extern __shared__ char sm[];
    const uint32_t smb = (uint32_t)__cvta_generic_to_shared(sm);
    __half* Bsh = (__half*)(sm + SM_BS);

    const int tid  = threadIdx.x;
    const int wid  = tid >> 5;
    const int lane = tid & 31;
    const int gid  = lane >> 2;
    const int warp_m = wid >> 1;
    const int warp_n = wid & 1;
    const int rbase  = warp_m * 32;

    for (int idx = tid; idx < C_OUT * C_IN * NBASIS; idx += 256) {
        int o   = idx / (C_IN * NBASIS);
        int rem = idx - o * (C_IN * NBASIS);
        int i   = rem / NBASIS;
        int k   = rem - i * NBASIS;
        uint32_t byte = (uint32_t)(k * 64 + o) * 128
                      + ((((uint32_t)i >> 3) ^ (uint32_t)(o & 7)) << 4)
                      + (i & 7) * 2;
        *(__half*)(sm + SM_W + byte) = __float2half_rn(W[idx]);
    }

    uint32_t a_base[2];
    #pragma unroll
    for (int mt = 0; mt < 2; mt++)
        a_base[mt] = smb + SM_AX
                   + (uint32_t)(rbase + mt * 16 + (lane & 15)) * 144
                   + ((lane >> 4) << 4);
    uint32_t b_base[2];
    int s_p[2];
    const int kh = (lane >> 3) & 1;
    #pragma unroll
    for (int p = 0; p < 2; p++) {
        int n_local = warp_n * 32 + p * 16 + ((lane >> 4) & 1) * 8 + (lane & 7);
        b_base[p] = smb + SM_W + (uint32_t)n_local * 128;
        s_p[p] = n_local & 7;
    }

    const int prow = tid >> 1;
    const int phf  = tid & 1;
    const int kb0  = phf ? 5 : 0;
    const int nby  = phf ? 4 : 5;

    uint32_t pk[16];
    float    by[5];

    int tile = blockIdx.x;
    {
        int t = tile * TILE_M + prow;
        if (t < T) {
            const float4* xp = (const float4*)(X + (size_t)t * C_IN + phf * 32);
            #pragma unroll
            for (int j = 0; j < 8; j++) {
                float4 v = xp[j];
                __half2 h0 = __floats2half2_rn(v.x, v.y);
                __half2 h1 = __floats2half2_rn(v.z, v.w);
                pk[2 * j]     = *(uint32_t*)&h0;
                pk[2 * j + 1] = *(uint32_t*)&h1;
            }
            #pragma unroll
            for (int j = 0; j < 5; j++)
                if (j < nby) by[j] = BARY[(size_t)t * NBASIS + kb0 + j];
        } else {
            #pragma unroll
            for (int j = 0; j < 16; j++) pk[j] = 0u;
            #pragma unroll
            for (int j = 0; j < 5; j++) by[j] = 0.0f;
        }
    }
    __syncthreads();

    int buf = 0;
    for (; tile < numTiles; tile += gridDim.x) {
        const int t0 = tile * TILE_M;
        {
            uint4* dst = (uint4*)(sm + SM_AX + prow * 144 + phf * 64);
            #pragma unroll
            for (int c = 0; c < 4; c++)
                dst[c] = make_uint4(pk[4 * c], pk[4 * c + 1], pk[4 * c + 2], pk[4 * c + 3]);
            __half* BsB = Bsh + buf * BS_HALFS;
            #pragma unroll
            for (int j = 0; j < 5; j++)
                if (j < nby) BsB[(kb0 + j) * 132 + prow] = __float2half_rn(by[j]);
        }
        __syncthreads();

        uint32_t afr[2][4][4];
        #pragma unroll
        for (int mt = 0; mt < 2; mt++)
            #pragma unroll
            for (int ks = 0; ks < 4; ks++)
                ldsm4(afr[mt][ks], a_base[mt] + ks * 32);
        __syncthreads();

        {
            int ntile = tile + gridDim.x;
            if (ntile < numTiles) {
                int t = ntile * TILE_M + prow;
                if (t < T) {
                    const float4* xp = (const float4*)(X + (size_t)t * C_IN + phf * 32);
                    #pragma unroll
                    for (int j = 0; j < 8; j++) {
                        float4 v = xp[j];
                        __half2 h0 = __floats2half2_rn(v.x, v.y);
                        __half2 h1 = __floats2half2_rn(v.z, v.w);
                        pk[2 * j]     = *(uint32_t*)&h0;
                        pk[2 * j + 1] = *(uint32_t*)&h1;
                    }
                    #pragma unroll
                    for (int j = 0; j < 5; j++)
                        if (j < nby) by[j] = BARY[(size_t)t * NBASIS + kb0 + j];
                } else {
                    #pragma unroll
                    for (int j = 0; j < 16; j++) pk[j] = 0u;
                    #pragma unroll
                    for (int j = 0; j < 5; j++) by[j] = 0.0f;
                }
            }
        }

        const __half* BsB = Bsh + buf * BS_HALFS;
        float acc[2][4][4];
        #pragma unroll
        for (int mt = 0; mt < 2; mt++)
            #pragma unroll
            for (int nt = 0; nt < 4; nt++)
                #pragma unroll
                for (int e = 0; e < 4; e++) acc[mt][nt][e] = 0.0f;

        #pragma unroll 1
        for (int kb = 0; kb < NBASIS; kb++) {
            uint32_t bb0[2], bb1[2];
            #pragma unroll
            for (int mt = 0; mt < 2; mt++) {
                int r = rbase + mt * 16 + gid;
                __half2 h0 = __half2half2(BsB[kb * 132 + r]);
                __half2 h1 = __half2half2(BsB[kb * 132 + r + 8]);
                bb0[mt] = *(uint32_t*)&h0;
                bb1[mt] = *(uint32_t*)&h1;
            }
            const uint32_t kb_off = (uint32_t)kb * 8192;
            #pragma unroll
            for (int ks = 0; ks < 4; ks++) {
                uint32_t sa0[4], sa1[4];
                sa0[0] = hmul2u(afr[0][ks][0], bb0[0]);
                sa0[1] = hmul2u(afr[0][ks][1], bb1[0]);
                sa0[2] = hmul2u(afr[0][ks][2], bb0[0]);
                sa0[3] = hmul2u(afr[0][ks][3], bb1[0]);
                sa1[0] = hmul2u(afr[1][ks][0], bb0[1]);
                sa1[1] = hmul2u(afr[1][ks][1], bb1[1]);
                sa1[2] = hmul2u(afr[1][ks][2], bb0[1]);
                sa1[3] = hmul2u(afr[1][ks][3], bb1[1]);
                #pragma unroll
                for (int p = 0; p < 2; p++) {
                    uint32_t b[4];
                    uint32_t chunk = (uint32_t)(((ks << 1) | kh) ^ s_p[p]) << 4;
                    ldsm4(b, b_base[p] + kb_off + chunk);
                    MMA16816(acc[0][2 * p],     sa0[0], sa0[1], sa0[2], sa0[3], b[0], b[1]);
                    MMA16816(acc[1][2 * p],     sa1[0], sa1[1], sa1[2], sa1[3], b[0], b[1]);
                    MMA16816(acc[0][2 * p + 1], sa0[0], sa0[1], sa0[2], sa0[3], b[2], b[3]);
                    MMA16816(acc[1][2 * p + 1], sa1[0], sa1[1], sa1[2], sa1[3], b[2], b[3]);
                }
            }
        }

        const int tid4 = lane & 3;
        #pragma unroll
        for (int mt = 0; mt < 2; mt++) {
            int t = t0 + rbase + mt * 16 + gid;
            #pragma unroll
            for (int nt = 0; nt < 4; nt++) {
                int col = warp_n * 32 + nt * 8 + tid4 * 2;
                if (t < T)
                    *(__half2*)&g_contrib[(size_t)t * C_OUT + col] =
                        __floats2half2_rn(acc[mt][nt][0], acc[mt][nt][1]);
                if (t + 8 < T)
                    *(__half2*)&g_contrib[(size_t)(t + 8) * C_OUT + col] =
                        __floats2half2_rn(acc[mt][nt][2], acc[mt][nt][3]);
            }
        }
        buf ^= 1;
    }
}

// ================= facet fallback (general counts) ==========================
__global__ void facet_kernel(const int* __restrict__ cnt,
                             const float* __restrict__ bias, int F) {
    if (g_flag) return;
    int tid  = threadIdx.x;
    int gw   = (blockIdx.x * blockDim.x + tid) >> 5;
    int lane = tid & 31;
    int nw   = (gridDim.x * blockDim.x) >> 5;
    float b0 = bias[2 * lane];
    float b1 = bias[2 * lane + 1];
    for (int f = gw; f < F; f += nw) {
        int start = g_offs[f];
        int c = cnt[f];
        float s0 = 0.0f, s1 = 0.0f;
        for (int r = 0; r < c; r++) {
            float2 u = __half22float2(((const __half2*)(g_contrib + (size_t)(start + r) * C_OUT))[lane]);
            s0 += u.x; s1 += u.y;
        }
        float inv = (c > 0) ? (1.0f / (float)c) : 0.0f;
        float v0 = fmaxf(s0 * inv + b0, 0.0f);
        float v1 = fmaxf(s1 * inv + b1, 0.0f);
        *(__half2*)&g_prebn[(size_t)f * C_OUT + 2 * lane] = __floats2half2_rn(v0, v1);
    }
}

// ================= BN stats over prebn =================
__global__ void stats_kernel(int F) {
    __shared__ float ssum[64], ssq[64];
    int tid = threadIdx.x;
    if (tid < 64) { ssum[tid] = 0.0f; ssq[tid] = 0.0f; }
    __syncthreads();

    int cp = tid & 31;
    float s0 = 0, s1 = 0, q0 = 0, q1 = 0;
    int idx = blockIdx.x * blockDim.x + tid;
    int total = F * 32;
    int stride = gridDim.x * blockDim.x;
    for (; idx < total; idx += stride) {
        float2 v = __half22float2(((const __half2*)g_prebn)[idx]);
        s0 += v.x; s1 += v.y;
        q0 += v.x * v.x; q1 += v.y * v.y;
    }
    atomicAdd(&ssum[2 * cp], s0); atomicAdd(&ssum[2 * cp + 1], s1);
    atomicAdd(&ssq[2 * cp],  q0); atomicAdd(&ssq[2 * cp + 1],  q1);
    __syncthreads();
    if (tid < 64) {
        atomicAdd(&g_stats[tid],      ssum[tid]);
        atomicAdd(&g_stats[64 + tid], ssq[tid]);
    }
}

// ================= batchnorm apply (fp16 in, fp32 out) =================
__global__ void bn_kernel(const float* __restrict__ gamma,
                          const float* __restrict__ beta,
                          float* __restrict__ out, int F) {
    int idx = blockIdx.x * blockDim.x + threadIdx.x;
    int total = F * (C_OUT / 4);
    float invF = 1.0f / (float)F;
    for (; idx < total; idx += gridDim.x * blockDim.x) {
        int o = (idx & 15) * 4;
        uint2 raw = *(const uint2*)&g_prebn[(size_t)idx * 4];
        float2 v01 = __half22float2(*(__half2*)&raw.x);
        float2 v23 = __half22float2(*(__half2*)&raw.y);
        float vv[4] = {v01.x, v01.y, v23.x, v23.y};
        float4 r;
        #pragma unroll
        for (int j = 0; j < 4; j++) {
            float mu  = g_stats[o + j] * invF;
            float var = g_stats[C_OUT + o + j] * invF - mu * mu;
            float sc  = rsqrtf(var + BN_EPS) * gamma[o + j];
            float bb  = beta[o + j];
            (&r.x)[j] = (vv[j] - mu) * sc + bb;
        }
        *(float4*)&out[(size_t)idx * 4] = r;
    }
}

// ================= launch =================
extern "C" void kernel_launch(void* const* d_in, const int* in_sizes, int n_in,
                              void* d_out, int out_size) {
    const float* X     = (const float*)d_in[0];
    const float* BARY  = (const float*)d_in[1];
    const float* W     = (const float*)d_in[2];
    const float* bias  = (const float*)d_in[3];
    const float* gamma = (const float*)d_in[4];
    const float* beta  = (const float*)d_in[5];
    const int*   cnt   = (const int*)d_in[6];

    int T = in_sizes[0] / C_IN;
    int F = in_sizes[6];
    int numTilesFB = (T + TILE_M - 1) / TILE_M;
    int numTilesFU = (T + TILE_TX - 1) / TILE_TX;

    int sms = 148;
    cudaDeviceGetAttribute(&sms, cudaDevAttrMultiProcessorCount, 0);
    cudaFuncSetAttribute(gemm_fused_kernel, cudaFuncAttributeMaxDynamicSharedMemorySize, SMEM_FUSED);
    cudaFuncSetAttribute(gemm_fallback_kernel, cudaFuncAttributeMaxDynamicSharedMemorySize, SMEM_GEMM);

    int nb = (F + 1023) / 1024;
    scan1_kernel<<<nb, 1024>>>(cnt, F);
    scan2_kernel<<<1, 1024>>>(nb);
    scan3_kernel<<<nb, 1024>>>(cnt, F);   // offsets + flag + zero stats

    gemm_fused_kernel<<<sms, 512, SMEM_FUSED>>>(X, BARY, W, bias, T, F, numTilesFU);
    gemm_fallback_kernel<<<2 * sms, 256, SMEM_GEMM>>>(X, BARY, W, T, numTilesFB);
    facet_kernel<<<2048, 256>>>(cnt, bias, F);

    stats_kernel<<<512, 256>>>(F);
    bn_kernel<<<2048, 256>>>(gamma, beta, (float*)d_out, F);
}

// round 15
// speedup vs baseline: 1.2239x; 1.2239x over previous
#include <cuda_runtime.h>
#include <cuda_fp16.h>
#include <math.h>
#include <stdint.h>

#define C_IN   64
#define C_OUT  64
#define NBASIS 9
#define TILE_M 128
#define MAX_T  1600000
#define MAX_F  400000
#define BN_EPS 1e-3f

// ---- scratch (device globals; no allocation allowed) ----
__device__ __half g_contrib[(size_t)MAX_T * C_OUT];  // fallback path only
__device__ __half g_prebn[(size_t)MAX_F * C_OUT];    // 51.2 MB (fp16)
__device__ __half g_wh[NBASIS * C_OUT * C_IN];       // 73728 B: W fp16, swizzled rows
__device__ int    g_offs[MAX_F];
__device__ int    g_blk[1024];
__device__ float  g_stats[2 * C_OUT];
__device__ int    g_flag;                             // 1 if all counts == 4

// ================= exclusive-scan of num_texture =================
__global__ void scan1_kernel(const int* __restrict__ cnt, int F) {
    __shared__ int s[1024];
    int tid = threadIdx.x;
    int f = blockIdx.x * 1024 + tid;
    int c = (f < F) ? cnt[f] : 0;
    s[tid] = c;
    __syncthreads();
    for (int off = 1; off < 1024; off <<= 1) {
        int v = (tid >= off) ? s[tid - off] : 0;
        __syncthreads();
        s[tid] += v;
        __syncthreads();
    }
    if (f < F) g_offs[f] = s[tid] - c;
    if (tid == 1023) g_blk[blockIdx.x] = s[1023];
}
__global__ void scan2_kernel(int nb) {
    __shared__ int s[1024];
    int tid = threadIdx.x;
    int c = (tid < nb) ? g_blk[tid] : 0;
    s[tid] = c;
    __syncthreads();
    for (int off = 1; off < 1024; off <<= 1) {
        int v = (tid >= off) ? s[tid - off] : 0;
        __syncthreads();
        s[tid] += v;
        __syncthreads();
    }
    if (tid < nb) g_blk[tid] = s[tid] - c;
    if (tid == 0) g_flag = 1;
}
__global__ void scan3_kernel(const int* __restrict__ cnt, int F) {
    int f = blockIdx.x * 1024 + threadIdx.x;
    bool ok = true;
    if (f < F) {
        g_offs[f] += g_blk[blockIdx.x];
        ok = (cnt[f] == 4);
    }
    if (blockIdx.x == 0 && threadIdx.x < 2 * C_OUT) g_stats[threadIdx.x] = 0.0f;
    if (!__syncthreads_and(ok ? 1 : 0)) {
        if (threadIdx.x == 0) g_flag = 0;
    }
}

// ================= W fp16 conversion to swizzled global layout ==============
// row = kb*64 + o (128 B each); within row: byte = ((i>>3)^(o&7))*16 + (i&7)*2
__global__ void wconv_kernel(const float* __restrict__ W) {
    int idx = blockIdx.x * 1024 + threadIdx.x;
    if (idx >= C_OUT * C_IN * NBASIS) return;
    int o   = idx / (C_IN * NBASIS);
    int rem = idx - o * (C_IN * NBASIS);
    int i   = rem / NBASIS;
    int k   = rem - i * NBASIS;
    uint32_t byte = (uint32_t)(k * 64 + o) * 128
                  + ((((uint32_t)i >> 3) ^ (uint32_t)(o & 7)) << 4)
                  + (i & 7) * 2;
    *(__half*)((char*)g_wh + byte) = __float2half_rn(W[idx]);
}

// ================= shared helpers =================
#define MMA16816(d, a0, a1, a2, a3, b0, b1)                                 \
    asm volatile(                                                           \
        "mma.sync.aligned.m16n8k16.row.col.f32.f16.f16.f32 "                \
        "{%0,%1,%2,%3},{%4,%5,%6,%7},{%8,%9},{%0,%1,%2,%3};"                \
        : "+f"((d)[0]), "+f"((d)[1]), "+f"((d)[2]), "+f"((d)[3])            \
        : "r"(a0), "r"(a1), "r"(a2), "r"(a3), "r"(b0), "r"(b1))

__device__ __forceinline__ void ldsm4(uint32_t* r, uint32_t addr) {
    asm volatile("ldmatrix.sync.aligned.m8n8.x4.shared.b16 {%0,%1,%2,%3}, [%4];"
                 : "=r"(r[0]), "=r"(r[1]), "=r"(r[2]), "=r"(r[3]) : "r"(addr));
}
__device__ __forceinline__ uint32_t hmul2u(uint32_t a, uint32_t b) {
    __half2 r = __hmul2(*(__half2*)&a, *(__half2*)&b);
    return *(uint32_t*)&r;
}
__device__ __forceinline__ uint32_t hfma2u(uint32_t a, uint32_t b, uint32_t c) {
    __half2 r = __hfma2(*(__half2*)&a, *(__half2*)&b, *(__half2*)&c);
    return *(uint32_t*)&r;
}
__device__ __forceinline__ void cpasync16(uint32_t dst, const void* src) {
    asm volatile("cp.async.cg.shared.global [%0], [%1], 16;"
                 :: "r"(dst), "l"(src) : "memory");
}
#define CP_COMMIT() asm volatile("cp.async.commit_group;" ::: "memory")
#define CP_WAIT1()  asm volatile("cp.async.wait_group 1;" ::: "memory")
#define CP_WAIT0()  asm volatile("cp.async.wait_group 0;" ::: "memory")

// ================= FUSED kernel: 2 CTAs/SM, W streamed per-kb ==============
// Z[f,:] = sum_j x[4f+j] ⊗ bary[4f+j] (fp16, SMEM).
// prebn[f,o] = relu((Z @ W^T)*0.25 + bias). Tile = 64 facets (256 textures).
// SMEM per CTA: Z 64x1168 = 74752; W ring 3x8192 = 24576  -> 99328 B.
#define TILE_TX   256
#define TILE_F    64
#define ZSTR      1168
#define SM_Z      0
#define SM_WB     74752
#define SMEM_FUSED 99328

__global__ void __launch_bounds__(256, 2) gemm_fused_kernel(
    const float* __restrict__ X,     // [T, 64]
    const float* __restrict__ BARY,  // [T, 9]
    const float* __restrict__ BIAS,  // [64]
    int T, int F, int numTiles)
{
    if (g_flag == 0) return;
    extern __shared__ char sm[];
    const uint32_t smb = (uint32_t)__cvta_generic_to_shared(sm);
    const char* whg = (const char*)g_wh;

    const int tid  = threadIdx.x;
    const int wid  = tid >> 5;
    const int lane = tid & 31;
    const int gid  = lane >> 2;
    const int tid4 = lane & 3;
    const int warp_m = wid >> 2;     // 0..1 : 32-facet band
    const int warp_n = wid & 3;      // 0..3 : 16-col band
    const int rbase  = warp_m * 32;

    // ---- bias regs ----
    float bia[2][2];
    #pragma unroll
    for (int ng = 0; ng < 2; ng++) {
        int col = warp_n * 16 + ng * 8 + tid4 * 2;
        bia[ng][0] = BIAS[col];
        bia[ng][1] = BIAS[col + 1];
    }

    // ---- LDSM addresses ----
    uint32_t aBase[2];
    #pragma unroll
    for (int mt = 0; mt < 2; mt++)
        aBase[mt] = smb + SM_Z
                  + (uint32_t)(rbase + mt * 16 + (lane & 15)) * ZSTR
                  + ((uint32_t)(lane >> 4) << 4);
    const int n_local = warp_n * 16 + ((lane >> 4) & 1) * 8 + (lane & 7);
    const int kh  = (lane >> 3) & 1;
    const int nsw = n_local & 7;
    const uint32_t bRowOff = (uint32_t)n_local * 128;   // within 8192B chunk

    // ---- construct ids ----
    const int fq = tid >> 2;         // 0..63
    const int q  = tid & 3;

    uint32_t xh[4][4][2];
    float    br[9];

    // prologue prefetch (tile 0)
    int tile = blockIdx.x;
    {
        #pragma unroll
        for (int j = 0; j < 4; j++) {
            int t = tile * TILE_TX + fq * 4 + j;
            if (t < T) {
                const float4* xp = (const float4*)(X + (size_t)t * C_IN + q * 4);
                #pragma unroll
                for (int cc = 0; cc < 4; cc++) {
                    float4 v = xp[cc * 4];
                    __half2 h0 = __floats2half2_rn(v.x, v.y);
                    __half2 h1 = __floats2half2_rn(v.z, v.w);
                    xh[j][cc][0] = *(uint32_t*)&h0;
                    xh[j][cc][1] = *(uint32_t*)&h1;
                }
            } else {
                #pragma unroll
                for (int cc = 0; cc < 4; cc++) { xh[j][cc][0] = 0u; xh[j][cc][1] = 0u; }
            }
        }
        int tb = tile * TILE_TX + fq * 4 + q;
        #pragma unroll
        for (int k = 0; k < NBASIS; k++)
            br[k] = (tb < T) ? BARY[(size_t)tb * NBASIS + k] : 0.0f;
    }

    int ib = 0;   // next buffer to fill (ring of 3)
    for (; tile < numTiles; tile += gridDim.x) {

        // ---- issue W chunks kb=0,1 (land during construct) ----
        int ib0 = ib, ib1 = (ib + 1) % 3;
        {
            uint32_t d0 = smb + SM_WB + (uint32_t)ib0 * 8192 + tid * 16;
            cpasync16(d0,        whg + 0 * 8192 + tid * 16);
            cpasync16(d0 + 4096, whg + 0 * 8192 + 4096 + tid * 16);
            CP_COMMIT();
            uint32_t d1 = smb + SM_WB + (uint32_t)ib1 * 8192 + tid * 16;
            cpasync16(d1,        whg + 1 * 8192 + tid * 16);
            cpasync16(d1 + 4096, whg + 1 * 8192 + 4096 + tid * 16);
            CP_COMMIT();
        }
        ib = (ib + 2) % 3;

        // ---- construct Z (fp16, quad-shuffle bary broadcast) ----
        {
            const uint32_t zbase = smb + SM_Z + (uint32_t)fq * ZSTR + q * 8;
            #pragma unroll
            for (int k = 0; k < NBASIS; k++) {
                uint32_t ac[4][2];
                #pragma unroll
                for (int j = 0; j < 4; j++) {
                    float bf = __shfl_sync(0xFFFFFFFFu, br[k], (lane & ~3) | j);
                    __half2 hb = __half2half2(__float2half_rn(bf));
                    uint32_t bb = *(uint32_t*)&hb;
                    #pragma unroll
                    for (int cc = 0; cc < 4; cc++) {
                        if (j == 0) {
                            ac[cc][0] = hmul2u(xh[0][cc][0], bb);
                            ac[cc][1] = hmul2u(xh[0][cc][1], bb);
                        } else {
                            ac[cc][0] = hfma2u(xh[j][cc][0], bb, ac[cc][0]);
                            ac[cc][1] = hfma2u(xh[j][cc][1], bb, ac[cc][1]);
                        }
                    }
                }
                #pragma unroll
                for (int cc = 0; cc < 4; cc++)
                    asm volatile("st.shared.v2.b32 [%0], {%1, %2};"
                                 :: "r"(zbase + k * 128 + cc * 32),
                                    "r"(ac[cc][0]), "r"(ac[cc][1]) : "memory");
            }
        }

        // ---- prefetch next tile X/bary (in flight during GEMM) ----
        {
            int ntile = tile + gridDim.x;
            if (ntile < numTiles) {
                #pragma unroll
                for (int j = 0; j < 4; j++) {
                    int t = ntile * TILE_TX + fq * 4 + j;
                    if (t < T) {
                        const float4* xp = (const float4*)(X + (size_t)t * C_IN + q * 4);
                        #pragma unroll
                        for (int cc = 0; cc < 4; cc++) {
                            float4 v = xp[cc * 4];
                            __half2 h0 = __floats2half2_rn(v.x, v.y);
                            __half2 h1 = __floats2half2_rn(v.z, v.w);
                            xh[j][cc][0] = *(uint32_t*)&h0;
                            xh[j][cc][1] = *(uint32_t*)&h1;
                        }
                    } else {
                        #pragma unroll
                        for (int cc = 0; cc < 4; cc++) { xh[j][cc][0] = 0u; xh[j][cc][1] = 0u; }
                    }
                }
                int tb = ntile * TILE_TX + fq * 4 + q;
                #pragma unroll
                for (int k = 0; k < NBASIS; k++)
                    br[k] = (tb < T) ? BARY[(size_t)tb * NBASIS + k] : 0.0f;
            }
        }

        // ---- GEMM over 9 kb chunks, triple-buffered cp.async pipeline ----
        float acc[2][2][4];
        #pragma unroll
        for (int mt = 0; mt < 2; mt++)
            #pragma unroll
            for (int ng = 0; ng < 2; ng++)
                #pragma unroll
                for (int e = 0; e < 4; e++) acc[mt][ng][e] = 0.0f;

        int rb = ib0;   // buffer of chunk kb=0
        #pragma unroll
        for (int kb = 0; kb < NBASIS; kb++) {
            if (kb < 8) { CP_WAIT1(); } else { CP_WAIT0(); }
            __syncthreads();   // chunk kb visible to all; also Z ready (kb==0),
                               // and prior reads of buffer 'ib' drained.
            if (kb + 2 <= 8) {
                uint32_t d = smb + SM_WB + (uint32_t)ib * 8192 + tid * 16;
                cpasync16(d,        whg + (size_t)(kb + 2) * 8192 + tid * 16);
                cpasync16(d + 4096, whg + (size_t)(kb + 2) * 8192 + 4096 + tid * 16);
                CP_COMMIT();
                ib = (ib + 1) % 3;
            }
            const uint32_t bChunk = smb + SM_WB + (uint32_t)rb * 8192 + bRowOff;
            const uint32_t kbA = (uint32_t)kb * 128;
            #pragma unroll
            for (int ks = 0; ks < 4; ks++) {
                uint32_t a0[4], a1[4], b[4];
                ldsm4(a0, aBase[0] + kbA + ks * 32);
                ldsm4(a1, aBase[1] + kbA + ks * 32);
                ldsm4(b, bChunk + ((uint32_t)(((ks << 1) | kh) ^ nsw) << 4));
                MMA16816(acc[0][0], a0[0], a0[1], a0[2], a0[3], b[0], b[1]);
                MMA16816(acc[0][1], a0[0], a0[1], a0[2], a0[3], b[2], b[3]);
                MMA16816(acc[1][0], a1[0], a1[1], a1[2], a1[3], b[0], b[1]);
                MMA16816(acc[1][1], a1[0], a1[1], a1[2], a1[3], b[2], b[3]);
            }
            rb = (rb + 1) % 3;
        }

        // ---- epilogue: mean + bias + relu -> prebn ----
        int f0 = tile * TILE_F + rbase;
        #pragma unroll
        for (int mt = 0; mt < 2; mt++) {
            int fA = f0 + mt * 16 + gid;
            #pragma unroll
            for (int ng = 0; ng < 2; ng++) {
                int col = warp_n * 16 + ng * 8 + tid4 * 2;
                if (fA < F) {
                    float v0 = fmaxf(acc[mt][ng][0] * 0.25f + bia[ng][0], 0.0f);
                    float v1 = fmaxf(acc[mt][ng][1] * 0.25f + bia[ng][1], 0.0f);
                    *(__half2*)&g_prebn[(size_t)fA * C_OUT + col] = __floats2half2_rn(v0, v1);
                }
                if (fA + 8 < F) {
                    float v0 = fmaxf(acc[mt][ng][2] * 0.25f + bia[ng][0], 0.0f);
                    float v1 = fmaxf(acc[mt][ng][3] * 0.25f + bia[ng][1], 0.0f);
                    *(__half2*)&g_prebn[(size_t)(fA + 8) * C_OUT + col] = __floats2half2_rn(v0, v1);
                }
            }
        }
        __syncthreads();   // protect Z for next tile's construct
    }
}

// ================= FALLBACK GEMM (general counts; R8/R12 core) =============
#define SM_W      0
#define SM_AX     73728
#define SM_BS     92160
#define BS_HALFS  1188
#define SMEM_GEMM 96912

__global__ void __launch_bounds__(256, 2) gemm_fallback_kernel(
    const float* __restrict__ X, const float* __restrict__ BARY,
    const float* __restrict__ W, int T, int numTiles)
{
    if (g_flag != 0) return;
    extern __shared__ char sm[];
    const uint32_t smb = (uint32_t)__cvta_generic_to_shared(sm);
    __half* Bsh = (__half*)(sm + SM_BS);

    const int tid  = threadIdx.x;
    const int wid  = tid >> 5;
    const int lane = tid & 31;
    const int gid  = lane >> 2;
    const int warp_m = wid >> 1;
    const int warp_n = wid & 1;
    const int rbase  = warp_m * 32;

    for (int idx = tid; idx < C_OUT * C_IN * NBASIS; idx += 256) {
        int o   = idx / (C_IN * NBASIS);
        int rem = idx - o * (C_IN * NBASIS);
        int i   = rem / NBASIS;
        int k   = rem - i * NBASIS;
        uint32_t byte = (uint32_t)(k * 64 + o) * 128
                      + ((((uint32_t)i >> 3) ^ (uint32_t)(o & 7)) << 4)
                      + (i & 7) * 2;
        *(__half*)(sm + SM_W + byte) = __float2half_rn(W[idx]);
    }

    uint32_t a_base[2];
    #pragma unroll
    for (int mt = 0; mt < 2; mt++)
        a_base[mt] = smb + SM_AX
                   + (uint32_t)(rbase + mt * 16 + (lane & 15)) * 144
                   + ((lane >> 4) << 4);
    uint32_t b_base[2];
    int s_p[2];
    const int kh = (lane >> 3) & 1;
    #pragma unroll
    for (int p = 0; p < 2; p++) {
        int n_local = warp_n * 32 + p * 16 + ((lane >> 4) & 1) * 8 + (lane & 7);
        b_base[p] = smb + SM_W + (uint32_t)n_local * 128;
        s_p[p] = n_local & 7;
    }

    const int prow = tid >> 1;
    const int phf  = tid & 1;
    const int kb0  = phf ? 5 : 0;
    const int nby  = phf ? 4 : 5;

    uint32_t pk[16];
    float    by[5];

    int tile = blockIdx.x;
    {
        int t = tile * TILE_M + prow;
        if (t < T) {
            const float4* xp = (const float4*)(X + (size_t)t * C_IN + phf * 32);
            #pragma unroll
            for (int j = 0; j < 8; j++) {
                float4 v = xp[j];
                __half2 h0 = __floats2half2_rn(v.x, v.y);
                __half2 h1 = __floats2half2_rn(v.z, v.w);
                pk[2 * j]     = *(uint32_t*)&h0;
                pk[2 * j + 1] = *(uint32_t*)&h1;
            }
            #pragma unroll
            for (int j = 0; j < 5; j++)
                if (j < nby) by[j] = BARY[(size_t)t * NBASIS + kb0 + j];
        } else {
            #pragma unroll
            for (int j = 0; j < 16; j++) pk[j] = 0u;
            #pragma unroll
            for (int j = 0; j < 5; j++) by[j] = 0.0f;
        }
    }
    __syncthreads();

    int buf = 0;
    for (; tile < numTiles; tile += gridDim.x) {
        const int t0 = tile * TILE_M;
        {
            uint4* dst = (uint4*)(sm + SM_AX + prow * 144 + phf * 64);
            #pragma unroll
            for (int c = 0; c < 4; c++)
                dst[c] = make_uint4(pk[4 * c], pk[4 * c + 1], pk[4 * c + 2], pk[4 * c + 3]);
            __half* BsB = Bsh + buf * BS_HALFS;
            #pragma unroll
            for (int j = 0; j < 5; j++)
                if (j < nby) BsB[(kb0 + j) * 132 + prow] = __float2half_rn(by[j]);
        }
        __syncthreads();

        uint32_t afr[2][4][4];
        #pragma unroll
        for (int mt = 0; mt < 2; mt++)
            #pragma unroll
            for (int ks = 0; ks < 4; ks++)
                ldsm4(afr[mt][ks], a_base[mt] + ks * 32);
        __syncthreads();

        {
            int ntile = tile + gridDim.x;
            if (ntile < numTiles) {
                int t = ntile * TILE_M + prow;
                if (t < T) {
                    const float4* xp = (const float4*)(X + (size_t)t * C_IN + phf * 32);
                    #pragma unroll
                    for (int j = 0; j < 8; j++) {
                        float4 v = xp[j];
                        __half2 h0 = __floats2half2_rn(v.x, v.y);
                        __half2 h1 = __floats2half2_rn(v.z, v.w);
                        pk[2 * j]     = *(uint32_t*)&h0;
                        pk[2 * j + 1] = *(uint32_t*)&h1;
                    }
                    #pragma unroll
                    for (int j = 0; j < 5; j++)
                        if (j < nby) by[j] = BARY[(size_t)t * NBASIS + kb0 + j];
                } else {
                    #pragma unroll
                    for (int j = 0; j < 16; j++) pk[j] = 0u;
                    #pragma unroll
                    for (int j = 0; j < 5; j++) by[j] = 0.0f;
                }
            }
        }

        const __half* BsB = Bsh + buf * BS_HALFS;
        float acc[2][4][4];
        #pragma unroll
        for (int mt = 0; mt < 2; mt++)
            #pragma unroll
            for (int nt = 0; nt < 4; nt++)
                #pragma unroll
                for (int e = 0; e < 4; e++) acc[mt][nt][e] = 0.0f;

        #pragma unroll 1
        for (int kb = 0; kb < NBASIS; kb++) {
            uint32_t bb0[2], bb1[2];
            #pragma unroll
            for (int mt = 0; mt < 2; mt++) {
                int r = rbase + mt * 16 + gid;
                __half2 h0 = __half2half2(BsB[kb * 132 + r]);
                __half2 h1 = __half2half2(BsB[kb * 132 + r + 8]);
                bb0[mt] = *(uint32_t*)&h0;
                bb1[mt] = *(uint32_t*)&h1;
            }
            const uint32_t kb_off = (uint32_t)kb * 8192;
            #pragma unroll
            for (int ks = 0; ks < 4; ks++) {
                uint32_t sa0[4], sa1[4];
                sa0[0] = hmul2u(afr[0][ks][0], bb0[0]);
                sa0[1] = hmul2u(afr[0][ks][1], bb1[0]);
                sa0[2] = hmul2u(afr[0][ks][2], bb0[0]);
                sa0[3] = hmul2u(afr[0][ks][3], bb1[0]);
                sa1[0] = hmul2u(afr[1][ks][0], bb0[1]);
                sa1[1] = hmul2u(afr[1][ks][1], bb1[1]);
                sa1[2] = hmul2u(afr[1][ks][2], bb0[1]);
                sa1[3] = hmul2u(afr[1][ks][3], bb1[1]);
                #pragma unroll
                for (int p = 0; p < 2; p++) {
                    uint32_t b[4];
                    uint32_t chunk = (uint32_t)(((ks << 1) | kh) ^ s_p[p]) << 4;
                    ldsm4(b, b_base[p] + kb_off + chunk);
                    MMA16816(acc[0][2 * p],     sa0[0], sa0[1], sa0[2], sa0[3], b[0], b[1]);
                    MMA16816(acc[1][2 * p],     sa1[0], sa1[1], sa1[2], sa1[3], b[0], b[1]);
                    MMA16816(acc[0][2 * p + 1], sa0[0], sa0[1], sa0[2], sa0[3], b[2], b[3]);
                    MMA16816(acc[1][2 * p + 1], sa1[0], sa1[1], sa1[2], sa1[3], b[2], b[3]);
                }
            }
        }

        const int tid4 = lane & 3;
        #pragma unroll
        for (int mt = 0; mt < 2; mt++) {
            int t = t0 + rbase + mt * 16 + gid;
            #pragma unroll
            for (int nt = 0; nt < 4; nt++) {
                int col = warp_n * 32 + nt * 8 + tid4 * 2;
                if (t < T)
                    *(__half2*)&g_contrib[(size_t)t * C_OUT + col] =
                        __floats2half2_rn(acc[mt][nt][0], acc[mt][nt][1]);
                if (t + 8 < T)
                    *(__half2*)&g_contrib[(size_t)(t + 8) * C_OUT + col] =
                        __floats2half2_rn(acc[mt][nt][2], acc[mt][nt][3]);
            }
        }
        buf ^= 1;
    }
}

// ================= facet fallback (general counts) ==========================
__global__ void facet_kernel(const int* __restrict__ cnt,
                             const float* __restrict__ bias, int F) {
    if (g_flag) return;
    int tid  = threadIdx.x;
    int gw   = (blockIdx.x * blockDim.x + tid) >> 5;
    int lane = tid & 31;
    int nw   = (gridDim.x * blockDim.x) >> 5;
    float b0 = bias[2 * lane];
    float b1 = bias[2 * lane + 1];
    for (int f = gw; f < F; f += nw) {
        int start = g_offs[f];
        int c = cnt[f];
        float s0 = 0.0f, s1 = 0.0f;
        for (int r = 0; r < c; r++) {
            float2 u = __half22float2(((const __half2*)(g_contrib + (size_t)(start + r) * C_OUT))[lane]);
            s0 += u.x; s1 += u.y;
        }
        float inv = (c > 0) ? (1.0f / (float)c) : 0.0f;
        float v0 = fmaxf(s0 * inv + b0, 0.0f);
        float v1 = fmaxf(s1 * inv + b1, 0.0f);
        *(__half2*)&g_prebn[(size_t)f * C_OUT + 2 * lane] = __floats2half2_rn(v0, v1);
    }
}

// ================= BN stats over prebn =================
__global__ void stats_kernel(int F) {
    __shared__ float ssum[64], ssq[64];
    int tid = threadIdx.x;
    if (tid < 64) { ssum[tid] = 0.0f; ssq[tid] = 0.0f; }
    __syncthreads();

    int cp = tid & 31;
    float s0 = 0, s1 = 0, q0 = 0, q1 = 0;
    int idx = blockIdx.x * blockDim.x + tid;
    int total = F * 32;
    int stride = gridDim.x * blockDim.x;
    for (; idx < total; idx += stride) {
        float2 v = __half22float2(((const __half2*)g_prebn)[idx]);
        s0 += v.x; s1 += v.y;
        q0 += v.x * v.x; q1 += v.y * v.y;
    }
    atomicAdd(&ssum[2 * cp], s0); atomicAdd(&ssum[2 * cp + 1], s1);
    atomicAdd(&ssq[2 * cp],  q0); atomicAdd(&ssq[2 * cp + 1],  q1);
    __syncthreads();
    if (tid < 64) {
        atomicAdd(&g_stats[tid],      ssum[tid]);
        atomicAdd(&g_stats[64 + tid], ssq[tid]);
    }
}

// ================= batchnorm apply (fp16 in, fp32 out) =================
__global__ void bn_kernel(const float* __restrict__ gamma,
                          const float* __restrict__ beta,
                          float* __restrict__ out, int F) {
    int idx = blockIdx.x * blockDim.x + threadIdx.x;
    int total = F * (C_OUT / 4);
    float invF = 1.0f / (float)F;
    for (; idx < total; idx += gridDim.x * blockDim.x) {
        int o = (idx & 15) * 4;
        uint2 raw = *(const uint2*)&g_prebn[(size_t)idx * 4];
        float2 v01 = __half22float2(*(__half2*)&raw.x);
        float2 v23 = __half22float2(*(__half2*)&raw.y);
        float vv[4] = {v01.x, v01.y, v23.x, v23.y};
        float4 r;
        #pragma unroll
        for (int j = 0; j < 4; j++) {
            float mu  = g_stats[o + j] * invF;
            float var = g_stats[C_OUT + o + j] * invF - mu * mu;
            float sc  = rsqrtf(var + BN_EPS) * gamma[o + j];
            float bb  = beta[o + j];
            (&r.x)[j] = (vv[j] - mu) * sc + bb;
        }
        *(float4*)&out[(size_t)idx * 4] = r;
    }
}

// ================= launch =================
extern "C" void kernel_launch(void* const* d_in, const int* in_sizes, int n_in,
                              void* d_out, int out_size) {
    const float* X     = (const float*)d_in[0];
    const float* BARY  = (const float*)d_in[1];
    const float* W     = (const float*)d_in[2];
    const float* bias  = (const float*)d_in[3];
    const float* gamma = (const float*)d_in[4];
    const float* beta  = (const float*)d_in[5];
    const int*   cnt   = (const int*)d_in[6];

    int T = in_sizes[0] / C_IN;
    int F = in_sizes[6];
    int numTilesFB = (T + TILE_M - 1) / TILE_M;
    int numTilesFU = (T + TILE_TX - 1) / TILE_TX;

    int sms = 148;
    cudaDeviceGetAttribute(&sms, cudaDevAttrMultiProcessorCount, 0);
    cudaFuncSetAttribute(gemm_fused_kernel, cudaFuncAttributeMaxDynamicSharedMemorySize, SMEM_FUSED);
    cudaFuncSetAttribute(gemm_fallback_kernel, cudaFuncAttributeMaxDynamicSharedMemorySize, SMEM_GEMM);

    int nb = (F + 1023) / 1024;
    scan1_kernel<<<nb, 1024>>>(cnt, F);
    scan2_kernel<<<1, 1024>>>(nb);
    scan3_kernel<<<nb, 1024>>>(cnt, F);   // offsets + flag + zero stats

    wconv_kernel<<<36, 1024>>>(W);

    gemm_fused_kernel<<<2 * sms, 256, SMEM_FUSED>>>(X, BARY, bias, T, F, numTilesFU);
    gemm_fallback_kernel<<<2 * sms, 256, SMEM_GEMM>>>(X, BARY, W, T, numTilesFB);
    facet_kernel<<<2048, 256>>>(cnt, bias, F);

    stats_kernel<<<512, 256>>>(F);
    bn_kernel<<<2048, 256>>>(gamma, beta, (float*)d_out, F);
}